// round 13
// baseline (speedup 1.0000x reference)
#include <cuda_runtime.h>
#include <stdint.h>

// Fixed problem shape (LengthRegulator_33285996544559):
//   x:   [B=32, T=512, C=512] float32
//   dur: [B=32, T=512] int32 in [0, 12)
//   out: [B, T_out, C] float32, T_out = out_size / (B*C)
#define B_DIM 32
#define T_DIM 512
#define C_DIM 512
#define FPB   16          // frames per block, 256 threads

// TMA-bulk-store variant: stage distinct source rows in SMEM once per block,
// then write each output frame as ONE 2KB cp.async.bulk burst. Probes whether
// the 59% DRAM plateau is controller-side write inefficiency (scattered 128B
// STG evictions) vs a hard write-path ceiling.
__global__ void __launch_bounds__(256) lr_tma_kernel(
    const float4* __restrict__ x4,
    float*        __restrict__ out,
    const int*    __restrict__ dur,
    int t_out)
{
    __shared__ int s_wsum[8];
    __shared__ int s_idx[FPB];
    __shared__ int s_slot[FPB];
    __shared__ int s_tok[FPB];
    __shared__ int s_nslots;
    __shared__ __align__(16) float4 s_buf[FPB * 128];   // up to 16 rows x 2KB

    const int row   = blockIdx.y;
    const int fbase = blockIdx.x * FPB;
    const int tid   = threadIdx.x;
    const int wid   = tid >> 5;
    const int lane  = tid & 31;

    // ---- 1) pair-scan of the row's 512 durations (3 syncthreads) ----
    int2 dd = ((const int2*)dur)[row * (T_DIM / 2) + tid];
    int d0 = dd.x > 0 ? dd.x : 0;
    int d1 = dd.y > 0 ? dd.y : 0;
    int p  = d0 + d1;

    int v = p;
    #pragma unroll
    for (int off = 1; off < 32; off <<= 1) {
        int n = __shfl_up_sync(0xffffffffu, v, off);
        if (lane >= off) v += n;
    }
    if (lane == 31) s_wsum[wid] = v;
    __syncthreads();
    if (wid == 0) {
        int w = (lane < 8) ? s_wsum[lane] : 0;
        #pragma unroll
        for (int off = 1; off < 8; off <<= 1) {
            int n = __shfl_up_sync(0xffffffffu, w, off);
            if (lane >= off) w += n;
        }
        if (lane < 8) s_wsum[lane] = w;
    }
    __syncthreads();

    const int pair_incl = ((wid > 0) ? s_wsum[wid - 1] : 0) + v;
    const int pair_excl = pair_incl - p;
    const int total     = s_wsum[7];

    // ---- 2) scatter token ids into this block's frame window ----
    const int fend = fbase + FPB;
    {
        int s = pair_excl, e = pair_excl + d0;
        int lo = s > fbase ? s : fbase;
        int hi = e < fend ? e : fend;
        for (int t = lo; t < hi; t++) s_idx[t - fbase] = 2 * tid;

        s = e; e = pair_incl;
        lo = s > fbase ? s : fbase;
        hi = e < fend ? e : fend;
        for (int t = lo; t < hi; t++) s_idx[t - fbase] = 2 * tid + 1;
    }
    if (tid < FPB && (fbase + tid) >= total)
        s_idx[tid] = T_DIM - 1;               // overflow -> last token
    __syncthreads();

    // ---- 3) dedup window tokens (s_idx is nondecreasing) into slots ----
    if (tid < FPB) {
        int slot = 0;
        for (int j = 1; j <= tid; j++)
            slot += (s_idx[j] != s_idx[j - 1]);
        s_slot[tid] = slot;
        if (tid == 0 || s_idx[tid] != s_idx[tid - 1])
            s_tok[slot] = s_idx[tid];
        if (tid == FPB - 1) s_nslots = slot + 1;
    }
    __syncthreads();

    // ---- 4) cooperative load of distinct rows into SMEM ----
    const int nslots = s_nslots;
    for (int i = tid; i < nslots * 128; i += 256) {
        int slot = i >> 7, c = i & 127;
        s_buf[i] = __ldg(&x4[((long long)(row * T_DIM + s_tok[slot]) << 7) + c]);
    }
    __syncthreads();

    // ---- 5) one 2KB TMA bulk store per frame (thread 0) ----
    if (tid == 0) {
        asm volatile("fence.proxy.async.shared::cta;" ::: "memory");
        uint32_t sbase;
        asm("{ .reg .u64 t; cvta.to.shared.u64 t, %1; cvt.u32.u64 %0, t; }"
            : "=r"(sbase) : "l"((const void*)s_buf));
        #pragma unroll
        for (int f = 0; f < FPB; f++) {
            int fr = fbase + f;
            if (fr >= t_out) break;
            const float* g = out + ((long long)(row * t_out + fr) << 9);
            uint32_t s = sbase + ((uint32_t)s_slot[f] << 11);
            asm volatile(
                "cp.async.bulk.global.shared::cta.bulk_group [%0], [%1], %2;"
                :: "l"(g), "r"(s), "r"(2048) : "memory");
        }
        asm volatile("cp.async.bulk.commit_group;" ::: "memory");
        asm volatile("cp.async.bulk.wait_group 0;" ::: "memory");
    }
}

extern "C" void kernel_launch(void* const* d_in, const int* in_sizes, int n_in,
                              void* d_out, int out_size) {
    const float* x   = (const float*)d_in[0];
    const int*   dur = (const int*)d_in[1];
    float*       out = (float*)d_out;

    const int t_out = out_size / (B_DIM * C_DIM);

    dim3 grid((t_out + FPB - 1) / FPB, B_DIM);
    lr_tma_kernel<<<grid, 256>>>((const float4*)x, out, dur, t_out);
}

// round 14
// speedup vs baseline: 1.1652x; 1.1652x over previous
#include <cuda_runtime.h>
#include <stdint.h>

// Fixed problem shape (LengthRegulator_33285996544559):
//   x:   [B=32, T=512, C=512] float32
//   dur: [B=32, T=512] int32 in [0, 12)
//   out: [B, T_out, C] float32, T_out = out_size / (B*C)
//
// CONVERGED KERNEL (13 rounds of probes; see commit log):
//   - fused single kernel: shfl pair-scan (3 syncthreads) + smem scatter +
//     warp-per-2-frames gather, 256-thread blocks
//   - 8x LDG.128 in flight before any store (MLP=8); dup-source skip reuses
//     registers when consecutive frames share a token (P ~ 0.82)
//   - __stcs streaming stores (stwt and TMA bulk stores both regressed;
//     write path is bandwidth-capped and path-independent)
// Floor: ~203 MB compulsory write stream at ~5.5 TB/s effective -> ~37 us.
#define B_DIM 32
#define T_DIM 512
#define C_DIM 512
#define FRAMES_PER_BLOCK 16   // 8 warps x 2 frames, 256 threads

__global__ void __launch_bounds__(256) lr_fused_kernel(
    const float4* __restrict__ x4,
    float4*       __restrict__ out4,
    const int*    __restrict__ dur,
    int t_out)
{
    __shared__ int s_wsum[8];
    __shared__ int s_idx[FRAMES_PER_BLOCK];

    const int row   = blockIdx.y;
    const int fbase = blockIdx.x * FRAMES_PER_BLOCK;
    const int tid   = threadIdx.x;
    const int wid   = tid >> 5;
    const int lane  = tid & 31;

    // ---- 1) scan: each thread owns a PAIR of durations (int2 load) ----
    int2 dd = ((const int2*)dur)[row * (T_DIM / 2) + tid];
    int d0 = dd.x > 0 ? dd.x : 0;
    int d1 = dd.y > 0 ? dd.y : 0;
    int p  = d0 + d1;

    int v = p;
    #pragma unroll
    for (int off = 1; off < 32; off <<= 1) {
        int n = __shfl_up_sync(0xffffffffu, v, off);
        if (lane >= off) v += n;
    }
    if (lane == 31) s_wsum[wid] = v;
    __syncthreads();
    if (wid == 0) {
        int w = (lane < 8) ? s_wsum[lane] : 0;
        #pragma unroll
        for (int off = 1; off < 8; off <<= 1) {
            int n = __shfl_up_sync(0xffffffffu, w, off);
            if (lane >= off) w += n;
        }
        if (lane < 8) s_wsum[lane] = w;
    }
    __syncthreads();

    const int pair_incl = ((wid > 0) ? s_wsum[wid - 1] : 0) + v;
    const int pair_excl = pair_incl - p;
    const int total     = s_wsum[7];

    // ---- 2) scatter into this block's frame window ----
    const int fend = fbase + FRAMES_PER_BLOCK;
    {
        int s = pair_excl, e = pair_excl + d0;
        int lo = s > fbase ? s : fbase;
        int hi = e < fend ? e : fend;
        for (int t = lo; t < hi; t++) s_idx[t - fbase] = 2 * tid;

        s = e; e = pair_incl;
        lo = s > fbase ? s : fbase;
        hi = e < fend ? e : fend;
        for (int t = lo; t < hi; t++) s_idx[t - fbase] = 2 * tid + 1;
    }
    if (tid < FRAMES_PER_BLOCK && (fbase + tid) >= total)
        s_idx[tid] = T_DIM - 1;               // overflow -> last token
    __syncthreads();

    // ---- 3) gather: warp w -> frames 2w, 2w+1, dup-source skip ----
    const int lf0 = wid << 1;
    const int f0  = fbase + lf0;
    if (f0 >= t_out) return;

    const bool has2 = (f0 + 1) < t_out;
    const int  i0 = s_idx[lf0];
    const int  i1 = s_idx[has2 ? lf0 + 1 : lf0];

    const float4* s0 = x4 + ((long long)(row * T_DIM + i0) << 7);

    float4 v0 = __ldg(&s0[lane]);
    float4 v1 = __ldg(&s0[lane + 32]);
    float4 v2 = __ldg(&s0[lane + 64]);
    float4 v3 = __ldg(&s0[lane + 96]);

    float4 u0 = v0, u1 = v1, u2 = v2, u3 = v3;
    if (i1 != i0) {                           // warp-uniform branch (~18%)
        const float4* s1 = x4 + ((long long)(row * T_DIM + i1) << 7);
        u0 = __ldg(&s1[lane]);
        u1 = __ldg(&s1[lane + 32]);
        u2 = __ldg(&s1[lane + 64]);
        u3 = __ldg(&s1[lane + 96]);
    }

    float4* dst0 = out4 + ((long long)(row * t_out + f0) << 7);
    __stcs(&dst0[lane],      v0);
    __stcs(&dst0[lane + 32], v1);
    __stcs(&dst0[lane + 64], v2);
    __stcs(&dst0[lane + 96], v3);

    if (has2) {
        float4* dst1 = dst0 + C_DIM / 4;
        __stcs(&dst1[lane],      u0);
        __stcs(&dst1[lane + 32], u1);
        __stcs(&dst1[lane + 64], u2);
        __stcs(&dst1[lane + 96], u3);
    }
}

extern "C" void kernel_launch(void* const* d_in, const int* in_sizes, int n_in,
                              void* d_out, int out_size) {
    const float* x   = (const float*)d_in[0];
    const int*   dur = (const int*)d_in[1];
    float*       out = (float*)d_out;

    const int t_out = out_size / (B_DIM * C_DIM);

    dim3 grid((t_out + FRAMES_PER_BLOCK - 1) / FRAMES_PER_BLOCK, B_DIM);
    lr_fused_kernel<<<grid, 256>>>(
        (const float4*)x, (float4*)out, dur, t_out);
}